// round 15
// baseline (speedup 1.0000x reference)
#include <cuda_runtime.h>
#include <cuda_fp16.h>
#include <math.h>

#define B_   4
#define S_   64
#define D_   512
#define H_   8
#define DH_  64
#define DFF_ 2048
#define L_   2
#define V_   32128
#define T_   16
#define M_   256
#define DD_  (D_*D_)
#define NEG_ (-1e9f)
#define NBLK 128
#define NTH  512

// ---------------- device scratch ----------------
__device__ float g_xe [M_*D_];
__device__ float g_h  [M_*D_];
__device__ float g_q  [M_*D_];
__device__ float g_k  [M_*D_];
__device__ float g_v  [M_*D_];
__device__ float g_at [M_*D_];
__device__ float g_ff [M_*DFF_];
__device__ float g_f2a[M_*D_];
__device__ float g_f2b[M_*D_];
__device__ float g_hs [M_*D_];
__device__ float g_cK [L_*M_*D_];
__device__ float g_cV [L_*M_*D_];
__device__ float g_dxA[B_*D_];
__device__ float g_dxB[B_*D_];
__device__ float g_dq [B_*D_];
__device__ float g_dso[B_*D_];
__device__ float g_dco[B_*D_];
__device__ float g_dff[B_*DFF_];
__device__ float g_kc [L_*B_*T_*D_];
__device__ float g_vc [L_*B_*T_*D_];
__device__ float g_pm [4*NBLK];
__device__ float g_ps [4*NBLK];
__device__ int   g_pi [4*NBLK];
// fp16 weight copies (decoder)
__device__ __half w_sq[L_*DD_];
__device__ __half w_sk[L_*DD_];
__device__ __half w_sv[L_*DD_];
__device__ __half w_so[L_*DD_];
__device__ __half w_cq[L_*DD_];
__device__ __half w_co[L_*DD_];
__device__ __half w_w1[L_*D_*DFF_];
__device__ __half w_w2[L_*DFF_*D_];
__device__ __half w_lm[D_*V_];
__device__ __half w_em[V_*D_];
// fp16 weight copies (encoder)
__device__ __half e_wq[L_*DD_];
__device__ __half e_wk[L_*DD_];
__device__ __half e_wv[L_*DD_];
__device__ __half e_wo[L_*DD_];
__device__ __half e_w1[L_*D_*DFF_];
__device__ __half e_w2[L_*DFF_*D_];
__device__ __half e_ck[L_*DD_];
__device__ __half e_cv[L_*DD_];
// barrier state
__device__ unsigned g_arr[NBLK*32];
__device__ __align__(128) volatile unsigned g_go;

// ---------------- shared memory ----------------
struct SDec {
    float h[8192];
    float red[2048];
    float sred[528];
    float p[64];
    float qv[64];
    int   si[512];
};
struct SEnc {
    float As[2][16][33];
    float Ws[2][16][64];
};
struct SAtt {
    float ks[64][64];
    float vs[64][64];
    float qs[16][64];
    float sc[16][68];
};
union SU { SDec d; SEnc e; SAtt a; };

__global__ void k_reset() {
    for (int i = threadIdx.x; i < NBLK*32; i += 128) g_arr[i] = 0u;
    if (threadIdx.x == 0) g_go = 0u;
}

// ---------------- grid barrier ----------------
__device__ __forceinline__ void gbar(unsigned ep) {
    __syncthreads();
    int tid = threadIdx.x, bi = blockIdx.x;
    if (tid == 0) {
        __threadfence();
        *(volatile unsigned*)&g_arr[bi*32] = ep;
    }
    if (bi == 0) {
        if (tid < NBLK)
            while (*(volatile unsigned*)&g_arr[tid*32] < ep) { }
        __syncthreads();
        if (tid == 0) { __threadfence(); g_go = ep; }
        __syncthreads();
    } else {
        if (tid == 0) {
            while (g_go < ep) { }
            __threadfence();
        }
        __syncthreads();
    }
}

// ---------------- fp32 -> fp16 conversion ----------------
__device__ __forceinline__ void cvt16(const float* __restrict__ s, __half* __restrict__ d, int n) {
    int base = blockIdx.x*NTH + threadIdx.x;
    #pragma unroll 4
    for (int i = base; i < n; i += NBLK*NTH) d[i] = __float2half(s[i]);
}

// ---------------- encoder SGEMM tile (fp16 W) ----------------
__device__ void dsgemm_h(SEnc& e, const float* __restrict__ A, int lda,
                         const __half* __restrict__ W,
                         float* __restrict__ C, const float* __restrict__ res,
                         int N, int K, int op, int mt, int nt) {
    int bx = nt * 64, by = mt * 32;
    int tid = threadIdx.x;
    int tx = tid & 15, ty = tid >> 4;
    int ar = tid >> 2, aq = tid & 3;
    int NT = K >> 4;

    float4 ra = make_float4(0,0,0,0);
    uint2 wr = make_uint2(0,0);
    if (tid < 128) ra = *(const float4*)&A[(by+ar)*lda + aq*4];
    if (tid < 256) wr = *(const uint2*)&W[ty*N + bx + tx*4];
    if (tid < 128) {
        e.As[0][aq*4+0][ar] = ra.x; e.As[0][aq*4+1][ar] = ra.y;
        e.As[0][aq*4+2][ar] = ra.z; e.As[0][aq*4+3][ar] = ra.w;
    }
    if (tid < 256) {
        __half2* hp = (__half2*)&wr;
        float2 f0 = __half22float2(hp[0]);
        float2 f1 = __half22float2(hp[1]);
        *(float4*)&e.Ws[0][ty][tx*4] = make_float4(f0.x, f0.y, f1.x, f1.y);
    }
    __syncthreads();

    float acc[2][4] = {};
    int buf = 0;
    for (int kt = 0; kt < NT; kt++) {
        bool pf = (kt + 1 < NT);
        if (pf) {
            int k0 = (kt + 1) << 4;
            if (tid < 128) ra = *(const float4*)&A[(by+ar)*lda + k0 + aq*4];
            if (tid < 256) wr = *(const uint2*)&W[(k0+ty)*N + bx + tx*4];
        }
        if (tid < 256) {
            #pragma unroll
            for (int kk = 0; kk < 16; kk++) {
                float a0 = e.As[buf][kk][ty*2+0];
                float a1 = e.As[buf][kk][ty*2+1];
                float4 b = *(const float4*)&e.Ws[buf][kk][tx*4];
                acc[0][0] = fmaf(a0, b.x, acc[0][0]); acc[0][1] = fmaf(a0, b.y, acc[0][1]);
                acc[0][2] = fmaf(a0, b.z, acc[0][2]); acc[0][3] = fmaf(a0, b.w, acc[0][3]);
                acc[1][0] = fmaf(a1, b.x, acc[1][0]); acc[1][1] = fmaf(a1, b.y, acc[1][1]);
                acc[1][2] = fmaf(a1, b.z, acc[1][2]); acc[1][3] = fmaf(a1, b.w, acc[1][3]);
            }
        }
        if (pf) {
            int nb = buf ^ 1;
            __syncthreads();
            if (tid < 128) {
                e.As[nb][aq*4+0][ar] = ra.x; e.As[nb][aq*4+1][ar] = ra.y;
                e.As[nb][aq*4+2][ar] = ra.z; e.As[nb][aq*4+3][ar] = ra.w;
            }
            if (tid < 256) {
                __half2* hp = (__half2*)&wr;
                float2 f0 = __half22float2(hp[0]);
                float2 f1 = __half22float2(hp[1]);
                *(float4*)&e.Ws[nb][ty][tx*4] = make_float4(f0.x, f0.y, f1.x, f1.y);
            }
            __syncthreads();
            buf = nb;
        }
    }
    if (tid < 256) {
        #pragma unroll
        for (int i = 0; i < 2; i++) {
            int m = by + ty*2 + i, n = bx + tx*4;
            float4 v = make_float4(acc[i][0], acc[i][1], acc[i][2], acc[i][3]);
            if (op & 1) {
                float4 r4 = *(const float4*)&res[m*N + n];
                v.x += r4.x; v.y += r4.y; v.z += r4.z; v.w += r4.w;
            }
            if (op & 2) {
                v.x = fmaxf(v.x, 0.f); v.y = fmaxf(v.y, 0.f);
                v.z = fmaxf(v.z, 0.f); v.w = fmaxf(v.w, 0.f);
            }
            *(float4*)&C[m*N + n] = v;
        }
    }
    __syncthreads();
}

// ---------------- encoder RMSNorm (2 rows/block) ----------------
__device__ void drms(SDec& sd, const float* __restrict__ x,
                     const float* __restrict__ fa, const float* __restrict__ fb,
                     const float* __restrict__ w,
                     float* __restrict__ xout, float* __restrict__ nout) {
    int tid = threadIdx.x;
    if (tid < 256) {
        int half = tid >> 7, lt = tid & 127;
        int r = blockIdx.x * 2 + half;
        float s = 0.f;
        for (int d = lt; d < D_; d += 128) {
            float v = x[r*D_ + d];
            if (fa) v += fa[r*D_ + d] + fb[r*D_ + d];
            sd.h[half*D_ + d] = v;
            s = fmaf(v, v, s);
        }
        for (int o = 16; o; o >>= 1) s += __shfl_xor_sync(0xffffffffu, s, o);
        if ((tid & 31) == 0) sd.sred[tid >> 5] = s;
    }
    __syncthreads();
    if (tid < 2) {
        float t = sd.sred[tid*4] + sd.sred[tid*4+1] + sd.sred[tid*4+2] + sd.sred[tid*4+3];
        sd.sred[8 + tid] = rsqrtf(t / (float)D_ + 1e-6f);
    }
    __syncthreads();
    if (tid < 256) {
        int half = tid >> 7, lt = tid & 127;
        int r = blockIdx.x * 2 + half;
        float rs = sd.sred[8 + half];
        for (int d = lt; d < D_; d += 128) {
            float v = sd.h[half*D_ + d];
            if (xout) xout[r*D_ + d] = v;
            nout[r*D_ + d] = v * rs * w[d];
        }
    }
    __syncthreads();
}

// ---------------- decode: load rms-normed x into smem h ----------------
__device__ __forceinline__ void loadx(SDec& sd, const float* __restrict__ x,
                                      const float* __restrict__ ln, int K) {
    int tid = threadIdx.x;
    if (ln) {
        int r = tid >> 7, c = tid & 127;
        float s = 0.f;
        for (int k = c; k < K; k += 128) { float v = x[r*K + k]; s = fmaf(v, v, s); }
        sd.sred[tid] = s;
        __syncthreads();
        if (tid < B_) {
            float t = 0.f;
            for (int i = 0; i < 128; i++) t += sd.sred[tid*128 + i];
            sd.sred[512 + tid] = rsqrtf(t / (float)K + 1e-6f);
        }
        __syncthreads();
        for (int i = tid; i < B_*K; i += NTH) {
            int r2 = i / K;
            sd.h[i] = x[i] * sd.sred[512 + r2] * ln[i - r2*K];
        }
    } else {
        for (int i = tid; i < B_*K; i += NTH) sd.h[i] = x[i];
    }
    __syncthreads();
}

// ---------------- decode: rms-normed fold of cur+dso+dco ----------------
__device__ __forceinline__ void loadx3(SDec& sd, const float* __restrict__ x,
                                       const float* __restrict__ ln) {
    int tid = threadIdx.x;
    int r = tid >> 7, c = tid & 127;
    float vv[4];
    float s = 0.f;
    #pragma unroll
    for (int q2 = 0; q2 < 4; q2++) {
        int k = c + q2*128;
        float v = x[r*D_ + k] + g_dso[r*D_ + k] + g_dco[r*D_ + k];
        vv[q2] = v;
        s = fmaf(v, v, s);
    }
    sd.sred[tid] = s;
    __syncthreads();
    if (tid < B_) {
        float t = 0.f;
        for (int i = 0; i < 128; i++) t += sd.sred[tid*128 + i];
        sd.sred[512 + tid] = rsqrtf(t / (float)D_ + 1e-6f);
    }
    __syncthreads();
    float rs = sd.sred[512 + r];
    #pragma unroll
    for (int q2 = 0; q2 < 4; q2++) {
        int k = c + q2*128;
        sd.h[r*D_ + k] = vv[q2] * rs * ln[k];
    }
    __syncthreads();
}

// ---------------- fp16 matvec: 16 cols/block, 32-way k-split -----------------
__device__ __forceinline__ void mv_hex(SDec& sd, const __half* __restrict__ W,
                                       float* __restrict__ C, int crs,
                                       const float* __restrict__ res,
                                       const float* __restrict__ res2,
                                       const float* __restrict__ res3,
                                       int N, int K, int relu, int col0) {
    int tid = threadIdx.x;
    int cp = tid & 7;
    int rh = (tid >> 3) & 1;
    int ks = tid >> 4;               // 0..31
    int kcnt = K >> 5;
    int kbeg = ks * kcnt;
    const __half* __restrict__ Wc = W + col0 + cp*2;
    int r0 = rh*2;
    const float* __restrict__ h0 = sd.h + r0*K;
    const float* __restrict__ h1 = sd.h + (r0+1)*K;
    float a00=0.f, a01=0.f, a10=0.f, a11=0.f;
    for (int kb = kbeg; kb < kbeg + kcnt; kb += 8) {
        __half2 w2[8];
        #pragma unroll
        for (int u = 0; u < 8; u++) w2[u] = *(const __half2*)(Wc + (size_t)(kb+u)*N);
        #pragma unroll
        for (int u = 0; u < 8; u++) {
            float2 wf = __half22float2(w2[u]);
            float hv0 = h0[kb+u], hv1 = h1[kb+u];
            a00 = fmaf(hv0, wf.x, a00); a01 = fmaf(hv0, wf.y, a01);
            a10 = fmaf(hv1, wf.x, a10); a11 = fmaf(hv1, wf.y, a11);
        }
    }
    int ci = cp*2;
    sd.red[ks*64 + (r0  )*16 + ci  ] = a00;
    sd.red[ks*64 + (r0  )*16 + ci+1] = a01;
    sd.red[ks*64 + (r0+1)*16 + ci  ] = a10;
    sd.red[ks*64 + (r0+1)*16 + ci+1] = a11;
    __syncthreads();
    sd.red[tid] += sd.red[tid + 512] + sd.red[tid + 1024] + sd.red[tid + 1536];
    __syncthreads();
    if (tid < 256) sd.red[tid] += sd.red[tid + 256];
    __syncthreads();
    if (tid < 128) sd.red[tid] += sd.red[tid + 128];
    __syncthreads();
    if (tid < 64) {
        float v = sd.red[tid] + sd.red[tid + 64];
        int r = tid >> 4, c = tid & 15;
        int colw = col0 + c;
        if (res)  v += res[r*crs + colw];
        if (res2) v += res2[r*D_ + colw];
        if (res3) v += res3[r*D_ + colw];
        if (relu) v = fmaxf(v, 0.f);
        C[r*crs + colw] = v;
    }
    __syncthreads();
}

// ---------------- self-attn + quartered fp16 out-proj (128 blocks) -----------
__device__ void self_attn(SDec& sd, int b, int hh, int qt, int t, int l) {
    int tid = threadIdx.x;
    if (tid < 64) sd.qv[tid] = g_dq[b*D_ + hh*DH_ + tid];
    __syncthreads();
    int nk = t + 1;
    if (tid < nk) {
        const float* kp = &g_kc[((size_t)(l*B_ + b)*T_ + tid)*D_ + hh*DH_];
        float sc = 0.f;
        #pragma unroll 16
        for (int d = 0; d < DH_; d++) sc = fmaf(sd.qv[d], kp[d], sc);
        sd.p[tid] = sc * 0.125f;
    }
    __syncthreads();
    if (tid < 32) {
        float v0 = (tid < nk) ? sd.p[tid] : -1e30f;
        float v1 = (tid + 32 < nk) ? sd.p[tid + 32] : -1e30f;
        float m = fmaxf(v0, v1);
        #pragma unroll
        for (int o = 16; o; o >>= 1) m = fmaxf(m, __shfl_xor_sync(0xffffffffu, m, o));
        float e0 = (tid < nk) ? __expf(v0 - m) : 0.f;
        float e1 = (tid + 32 < nk) ? __expf(v1 - m) : 0.f;
        float su = e0 + e1;
        #pragma unroll
        for (int o = 16; o; o >>= 1) su += __shfl_xor_sync(0xffffffffu, su, o);
        float inv = 1.f / su;
        if (tid < nk) sd.p[tid] = e0 * inv;
        if (tid + 32 < nk) sd.p[tid + 32] = e1 * inv;
    }
    __syncthreads();
    if (tid < 64) {
        float o = 0.f;
        for (int j = 0; j < nk; j++)
            o = fmaf(sd.p[j], g_vc[((size_t)(l*B_ + b)*T_ + j)*D_ + hh*DH_ + tid], o);
        sd.sred[256 + tid] = o;
    }
    __syncthreads();
    // quartered out-proj: cols qt*128..+127, 4-way d-split
    {
        int colI = tid & 127, kp4 = tid >> 7;
        const __half* __restrict__ Wc =
            w_so + (size_t)l*DD_ + (size_t)(hh*64 + kp4*16)*D_ + qt*128 + colI;
        const float* __restrict__ dv = &sd.sred[256 + kp4*16];
        float a = 0.f;
        #pragma unroll
        for (int d0 = 0; d0 < 16; d0++)
            a = fmaf(dv[d0], __half2float(Wc[(size_t)d0*D_]), a);
        sd.red[kp4*128 + colI] = a;
    }
    __syncthreads();
    if (tid < 128) {
        float v = sd.red[tid] + sd.red[128+tid] + sd.red[256+tid] + sd.red[384+tid];
        atomicAdd(&g_dso[b*D_ + qt*128 + tid], v);
    }
    __syncthreads();
}

// ---------------- cross-attn + quartered fp16 out-proj (128 blocks) ----------
__device__ void cross_attn(SDec& sd, int b, int hh, int qt, int l,
                           const float* __restrict__ cur,
                           const float* __restrict__ mask,
                           const float* __restrict__ ln) {
    int tid = threadIdx.x;
    float v = cur[b*D_ + tid] + g_dso[b*D_ + tid];
    float s = v * v;
    #pragma unroll
    for (int o = 16; o; o >>= 1) s += __shfl_xor_sync(0xffffffffu, s, o);
    if ((tid & 31) == 0) sd.sred[tid >> 5] = s;
    __syncthreads();
    if (tid == 0) {
        float t = 0.f;
        #pragma unroll
        for (int i = 0; i < 16; i++) t += sd.sred[i];
        sd.sred[16] = rsqrtf(t / (float)D_ + 1e-6f);
    }
    __syncthreads();
    sd.h[tid] = v * sd.sred[16] * ln[tid];
    __syncthreads();
    // q matvec (fp16): 32 col-pairs x 16 k-splits
    {
        int c2 = tid & 31, ks = tid >> 5;
        const __half* __restrict__ Wqc = w_cq + (size_t)l*DD_ + hh*64 + c2*2;
        int kb0 = ks * 32;
        float a0 = 0.f, a1 = 0.f;
        #pragma unroll
        for (int kk = 0; kk < 32; kk += 8) {
            __half2 w2[8];
            #pragma unroll
            for (int u = 0; u < 8; u++) w2[u] = *(const __half2*)(Wqc + (size_t)(kb0+kk+u)*D_);
            #pragma unroll
            for (int u = 0; u < 8; u++) {
                float2 wf = __half22float2(w2[u]);
                float hv = sd.h[kb0+kk+u];
                a0 = fmaf(hv, wf.x, a0);
                a1 = fmaf(hv, wf.y, a1);
            }
        }
        sd.red[ks*64 + c2*2    ] = a0;
        sd.red[ks*64 + c2*2 + 1] = a1;
    }
    __syncthreads();
    #pragma unroll
    for (int s2 = 512; s2 >= 64; s2 >>= 1) {
        if (tid < s2) sd.red[tid] += sd.red[tid + s2];
        __syncthreads();
    }
    if (tid < 64) sd.qv[tid] = sd.red[tid];
    __syncthreads();
    if (tid < S_) {
        const float* kp = &g_cK[(size_t)l*M_*D_ + (size_t)(b*S_ + tid)*D_ + hh*DH_];
        float sc = 0.f;
        #pragma unroll 16
        for (int d = 0; d < DH_; d++) sc = fmaf(sd.qv[d], kp[d], sc);
        sd.p[tid] = sc * 0.125f + (1.f - mask[b*S_ + tid]) * NEG_;
    }
    __syncthreads();
    if (tid < 32) {
        float v0 = sd.p[tid], v1 = sd.p[tid + 32];
        float m = fmaxf(v0, v1);
        #pragma unroll
        for (int o = 16; o; o >>= 1) m = fmaxf(m, __shfl_xor_sync(0xffffffffu, m, o));
        float e0 = __expf(v0 - m), e1 = __expf(v1 - m);
        float su = e0 + e1;
        #pragma unroll
        for (int o = 16; o; o >>= 1) su += __shfl_xor_sync(0xffffffffu, su, o);
        float inv = 1.f / su;
        sd.p[tid] = e0 * inv;
        sd.p[tid + 32] = e1 * inv;
    }
    __syncthreads();
    if (tid < 64) {
        float o = 0.f;
        for (int j = 0; j < S_; j++)
            o = fmaf(sd.p[j], g_cV[(size_t)l*M_*D_ + (size_t)(b*S_ + j)*D_ + hh*DH_ + tid], o);
        sd.sred[256 + tid] = o;
    }
    __syncthreads();
    {
        int colI = tid & 127, kp4 = tid >> 7;
        const __half* __restrict__ Wc =
            w_co + (size_t)l*DD_ + (size_t)(hh*64 + kp4*16)*D_ + qt*128 + colI;
        const float* __restrict__ dv = &sd.sred[256 + kp4*16];
        float a = 0.f;
        #pragma unroll
        for (int d0 = 0; d0 < 16; d0++)
            a = fmaf(dv[d0], __half2float(Wc[(size_t)d0*D_]), a);
        sd.red[kp4*128 + colI] = a;
    }
    __syncthreads();
    if (tid < 128) {
        float vsum = sd.red[tid] + sd.red[128+tid] + sd.red[256+tid] + sd.red[384+tid];
        atomicAdd(&g_dco[b*D_ + qt*128 + tid], vsum);
    }
    __syncthreads();
}

// ==================== megakernel ====================
__global__ void __launch_bounds__(NTH, 1)
k_mega(const int* __restrict__ ids, const float* __restrict__ mask,
       const float* __restrict__ emb,
       const float* __restrict__ enc_wq, const float* __restrict__ enc_wk,
       const float* __restrict__ enc_wv, const float* __restrict__ enc_wo,
       const float* __restrict__ enc_ln1,
       const float* __restrict__ enc_w1, const float* __restrict__ enc_w2,
       const float* __restrict__ enc_ln2, const float* __restrict__ enc_lnf,
       const float* __restrict__ dec_sq, const float* __restrict__ dec_sk,
       const float* __restrict__ dec_sv, const float* __restrict__ dec_so,
       const float* __restrict__ dec_ln1,
       const float* __restrict__ dec_cq, const float* __restrict__ dec_ck,
       const float* __restrict__ dec_cv, const float* __restrict__ dec_co,
       const float* __restrict__ dec_ln2,
       const float* __restrict__ dec_w1, const float* __restrict__ dec_w2,
       const float* __restrict__ dec_ln3, const float* __restrict__ dec_lnf,
       const float* __restrict__ lm_head,
       float* __restrict__ out) {
    __shared__ SU u;
    int bi  = blockIdx.x;
    int tid = threadIdx.x;
    unsigned ep = 0;
    float* lgs = &u.d.red[1024];

    // ---- fp32 -> fp16 weight conversion ----
    cvt16(dec_sq, w_sq, L_*DD_);
    cvt16(dec_sk, w_sk, L_*DD_);
    cvt16(dec_sv, w_sv, L_*DD_);
    cvt16(dec_so, w_so, L_*DD_);
    cvt16(dec_cq, w_cq, L_*DD_);
    cvt16(dec_co, w_co, L_*DD_);
    cvt16(dec_w1, w_w1, L_*D_*DFF_);
    cvt16(dec_w2, w_w2, L_*DFF_*D_);
    cvt16(lm_head, w_lm, D_*V_);
    cvt16(emb, w_em, V_*D_);
    cvt16(enc_wq, e_wq, L_*DD_);
    cvt16(enc_wk, e_wk, L_*DD_);
    cvt16(enc_wv, e_wv, L_*DD_);
    cvt16(enc_wo, e_wo, L_*DD_);
    cvt16(enc_w1, e_w1, L_*D_*DFF_);
    cvt16(enc_w2, e_w2, L_*DFF_*D_);
    cvt16(dec_ck, e_ck, L_*DD_);
    cvt16(dec_cv, e_cv, L_*DD_);

    // ================= encoder =================
    {
        int r0 = bi * 2;
        g_xe[r0*D_ + tid]     = emb[ids[r0]*D_ + tid];
        g_xe[(r0+1)*D_ + tid] = emb[ids[r0+1]*D_ + tid];
    }
    gbar(++ep);

    for (int l = 0; l < L_; l++) {
        if (l == 0) drms(u.d, g_xe, nullptr, nullptr, enc_ln1, nullptr, g_h);
        else        drms(u.d, g_xe, g_f2a, g_f2b, enc_ln1 + l*D_, g_xe, g_h);
        gbar(++ep);
        {
            int z = bi >> 6, tt = bi & 63;
            const __half* W = (z == 0) ? e_wq + l*DD_ : e_wk + l*DD_;
            float* C = (z == 0) ? g_q : g_k;
            dsgemm_h(u.e, g_h, D_, W, C, nullptr, D_, D_, 0, tt >> 3, tt & 7);
        }
        if (bi < 64)
            dsgemm_h(u.e, g_h, D_, e_wv + l*DD_, g_v, nullptr, D_, D_, 0, bi >> 3, bi & 7);
        gbar(++ep);
        {
            int b = bi >> 5, hh = (bi >> 2) & 7, qq = bi & 3;
            for (int i = tid; i < 4096; i += NTH) {
                int j = i >> 6, d = i & 63;
                u.a.ks[j][d ^ (j & 31)] = g_k[(b*64 + j)*D_ + hh*64 + d];
                u.a.vs[j][d]            = g_v[(b*64 + j)*D_ + hh*64 + d];
            }
            for (int i = tid; i < 1024; i += NTH) {
                int r = i >> 6, d = i & 63;
                u.a.qs[r][d] = g_q[(b*64 + qq*16 + r)*D_ + hh*64 + d];
            }
            __syncthreads();
            {
                int i = tid >> 5, j0 = (tid & 31) * 2;
                float a0 = 0.f, a1 = 0.f;
                #pragma unroll 8
                for (int d = 0; d < 64; d++) {
                    float qv = u.a.qs[i][d];
                    a0 = fmaf(qv, u.a.ks[j0+0][d ^ ((j0+0) & 31)], a0);
                    a1 = fmaf(qv, u.a.ks[j0+1][d ^ ((j0+1) & 31)], a1);
                }
                u.a.sc[i][j0+0] = a0 * 0.125f + (1.f - mask[b*64 + j0+0]) * NEG_;
                u.a.sc[i][j0+1] = a1 * 0.125f + (1.f - mask[b*64 + j0+1]) * NEG_;
            }
            __syncthreads();
            if (tid < 16) {
                int i = tid;
                float m = -1e30f;
                for (int j = 0; j < 64; j++) m = fmaxf(m, u.a.sc[i][j]);
                float su = 0.f;
                for (int j = 0; j < 64; j++) { float e = __expf(u.a.sc[i][j] - m); u.a.sc[i][j] = e; su += e; }
                float inv = 1.f / su;
                for (int j = 0; j < 64; j++) u.a.sc[i][j] *= inv;
            }
            __syncthreads();
            {
                int i = tid >> 5, d0 = (tid & 31) * 2;
                float o0 = 0.f, o1 = 0.f;
                #pragma unroll 8
                for (int j = 0; j < 64; j++) {
                    float p = u.a.sc[i][j];
                    o0 = fmaf(p, u.a.vs[j][d0+0], o0);
                    o1 = fmaf(p, u.a.vs[j][d0+1], o1);
                }
                float* op = &g_at[(b*64 + qq*16 + i)*D_ + hh*64 + d0];
                op[0] = o0; op[1] = o1;
            }
            __syncthreads();
        }
        gbar(++ep);
        if (bi < 64)
            dsgemm_h(u.e, g_at, D_, e_wo + l*DD_, g_xe, g_xe, D_, D_, 1, bi >> 3, bi & 7);
        gbar(++ep);
        drms(u.d, g_xe, nullptr, nullptr, enc_ln2 + l*D_, nullptr, g_h);
        gbar(++ep);
        dsgemm_h(u.e, g_h, D_, e_w1 + l*D_*DFF_, g_ff, nullptr, DFF_, D_, 2, bi >> 5, bi & 31);
        {
            int tile = bi + 128;
            dsgemm_h(u.e, g_h, D_, e_w1 + l*D_*DFF_, g_ff, nullptr, DFF_, D_, 2, tile >> 5, tile & 31);
        }
        gbar(++ep);
        {
            int half = bi >> 6, tt = bi & 63;
            const __half* W2 = e_w2 + l*DFF_*D_ + half*1024*D_;
            const float* A2 = g_ff + half*1024;
            float* C2 = half ? g_f2b : g_f2a;
            dsgemm_h(u.e, A2, DFF_, W2, C2, nullptr, D_, 1024, 0, tt >> 3, tt & 7);
        }
        gbar(++ep);
    }
    drms(u.d, g_xe, g_f2a, g_f2b, enc_lnf, nullptr, g_hs);
    gbar(++ep);
    for (int round = 0; round < 2; round++) {
        int tile = bi + round*128;
        int l = tile >> 7, rem = tile & 127, mat = rem >> 6, tt = rem & 63;
        const __half* W = mat ? e_cv + l*DD_ : e_ck + l*DD_;
        float* C = mat ? g_cV + l*M_*D_ : g_cK + l*M_*D_;
        dsgemm_h(u.e, g_hs, D_, W, C, nullptr, D_, D_, 0, tt >> 3, tt & 7);
    }
    if (bi < B_) g_dxA[bi*D_ + tid] = emb[tid];   // PAD_ID = 0
    gbar(++ep);

    // ================= decoder =================
    float* cur = g_dxA;
    float* nxt = g_dxB;
    for (int t = 0; t < T_; t++) {
        for (int l = 0; l < L_; l++) {
            float* kcb = &g_kc[(size_t)(l*B_*T_ + t) * D_];
            float* vcb = &g_vc[(size_t)(l*B_*T_ + t) * D_];
            // ---- S1: K,V,Q projections + zero deltas ----
            if (bi < 96) loadx(u.d, cur, dec_ln1 + l*D_, D_);
            if (tid < 16) { g_dso[bi*16 + tid] = 0.f; g_dco[bi*16 + tid] = 0.f; }
            if (l == 0 && tid < 16) nxt[bi*16 + tid] = 0.f;
            if (bi < 32)
                mv_hex(u.d, w_sk + (size_t)l*DD_, kcb, T_*D_, nullptr, nullptr, nullptr, D_, D_, 0, bi*16);
            else if (bi < 64)
                mv_hex(u.d, w_sv + (size_t)l*DD_, vcb, T_*D_, nullptr, nullptr, nullptr, D_, D_, 0, (bi-32)*16);
            else if (bi < 96)
                mv_hex(u.d, w_sq + (size_t)l*DD_, g_dq, D_, nullptr, nullptr, nullptr, D_, D_, 0, (bi-64)*16);
            gbar(++ep);
            // ---- S2: self-attn + quartered out-proj (128 blocks) ----
            self_attn(u.d, bi >> 5, (bi >> 2) & 7, bi & 3, t, l);
            gbar(++ep);
            // ---- S3: cross attn + quartered out-proj (128 blocks) ----
            cross_attn(u.d, bi >> 5, (bi >> 2) & 7, bi & 3, l, cur, mask, dec_ln2 + l*D_);
            gbar(++ep);
            // ---- S4: FFN1 (relu) ----
            loadx3(u.d, cur, dec_ln3 + l*D_);
            mv_hex(u.d, w_w1 + (size_t)l*D_*DFF_, g_dff, DFF_, nullptr, nullptr, nullptr, DFF_, D_, 1, bi*16);
            gbar(++ep);
            // ---- S5: FFN2 + residuals (32 blocks) ----
            if (bi < 32) {
                loadx(u.d, g_dff, nullptr, DFF_);
                mv_hex(u.d, w_w2 + (size_t)l*DFF_*D_, cur, D_, cur, g_dso, g_dco, D_, DFF_, 0, bi*16);
            }
            gbar(++ep);
        }
        // ---- lm_head (fp16) + per-block softmax partials ----
        {
            loadx(u.d, cur, dec_lnf, D_);
            int half = tid >> 8, cc = tid & 255;
            float a0 = 0.f, a1 = 0.f, a2 = 0.f, a3 = 0.f;
            if (cc < 251) {
                const __half* __restrict__ Wc = w_lm + (size_t)half*256*V_ + bi*251 + cc;
                const float* __restrict__ hh = u.d.h + half*256;
                for (int k = 0; k < 256; k += 16) {
                    float w[16];
                    #pragma unroll
                    for (int uu = 0; uu < 16; uu++) w[uu] = __half2float(Wc[(size_t)(k + uu) * V_]);
                    #pragma unroll
                    for (int uu = 0; uu < 16; uu++) {
                        a0 = fmaf(hh[k+uu],          w[uu], a0);
                        a1 = fmaf(hh[D_ + k+uu],     w[uu], a1);
                        a2 = fmaf(hh[2*D_ + k+uu],   w[uu], a2);
                        a3 = fmaf(hh[3*D_ + k+uu],   w[uu], a3);
                    }
                }
            }
            u.d.red[half*1024 + 0*256 + cc] = a0;
            u.d.red[half*1024 + 1*256 + cc] = a1;
            u.d.red[half*1024 + 2*256 + cc] = a2;
            u.d.red[half*1024 + 3*256 + cc] = a3;
            __syncthreads();
            float lgr[4];
            if (tid < 251) {
                #pragma unroll
                for (int r = 0; r < 4; r++)
                    lgr[r] = u.d.red[r*256 + tid] + u.d.red[1024 + r*256 + tid];
            }
            __syncthreads();
            if (tid < 251) {
                #pragma unroll
                for (int r = 0; r < 4; r++) lgs[r*252 + tid] = lgr[r];
            }
            __syncthreads();
            int r = tid >> 7, j = tid & 127;
            float v0 = lgs[r*252 + j];
            int   i0 = bi*251 + j;
            if (j + 128 < 251) {
                float v1 = lgs[r*252 + j + 128];
                if (v1 > v0) { v0 = v1; i0 = bi*251 + j + 128; }
            }
            u.d.red[tid] = v0; u.d.si[tid] = i0;
            __syncthreads();
            for (int s = 64; s; s >>= 1) {
                if (j < s) {
                    float xo = u.d.red[tid + s]; int io = u.d.si[tid + s];
                    if (xo > u.d.red[tid] || (xo == u.d.red[tid] && io < u.d.si[tid])) {
                        u.d.red[tid] = xo; u.d.si[tid] = io;
                    }
                }
                __syncthreads();
            }
            float Mb = u.d.red[r*128];
            float e = __expf(lgs[r*252 + j] - Mb);
            if (j + 128 < 251) e += __expf(lgs[r*252 + j + 128] - Mb);
            u.d.red[512 + tid] = e;
            __syncthreads();
            for (int s = 64; s; s >>= 1) {
                if (j < s) u.d.red[512 + tid] += u.d.red[512 + tid + s];
                __syncthreads();
            }
            if (j == 0) {
                g_pm[r*NBLK + bi] = Mb;
                g_ps[r*NBLK + bi] = u.d.red[512 + r*128];
                g_pi[r*NBLK + bi] = u.d.si[r*128];
            }
            __syncthreads();
        }
        gbar(++ep);
        // ---- combine partials + probs + output + ynext (fp16 emb) ----
        {
            int r = tid >> 7, b = tid & 127;
            u.d.red[tid] = g_pm[r*NBLK + b];
            u.d.si[tid]  = g_pi[r*NBLK + b];
            float sb = g_ps[r*NBLK + b];
            __syncthreads();
            for (int s = 64; s; s >>= 1) {
                if (b < s) {
                    float xo = u.d.red[tid + s]; int io = u.d.si[tid + s];
                    if (xo > u.d.red[tid] || (xo == u.d.red[tid] && io < u.d.si[tid])) {
                        u.d.red[tid] = xo; u.d.si[tid] = io;
                    }
                }
                __syncthreads();
            }
            float Mr = u.d.red[r*128];
            u.d.red[512 + tid] = sb * __expf(g_pm[r*NBLK + b] - Mr);
            __syncthreads();
            for (int s = 64; s; s >>= 1) {
                if (b < s) u.d.red[512 + tid] += u.d.red[512 + tid + s];
                __syncthreads();
            }
            if (b == 0) {
                u.d.sred[r] = Mr;
                u.d.sred[4 + r] = 1.f / u.d.red[512 + r*128];
            }
            __syncthreads();
            if (bi == 0 && tid < 4)
                out[B_*T_*V_ + tid*T_ + t] = (u.d.si[tid*128] == 0) ? 1.0f : 0.0f;
            if (tid < 251) {
                #pragma unroll
                for (int rr = 0; rr < 4; rr++) {
                    float pv = __expf(lgs[rr*252 + tid] - u.d.sred[rr]) * u.d.sred[4 + rr];
                    out[(rr*T_ + t)*V_ + bi*251 + tid] = pv;
                    u.d.h[rr*251 + tid] = pv;
                }
            }
            __syncthreads();
            int v0 = bi * 251;
            int c = tid;
            float A0 = 0.f, A1 = 0.f, A2 = 0.f, A3 = 0.f;
            int j2 = 0;
            for (; j2 + 8 <= 251; j2 += 8) {
                float e8[8];
                #pragma unroll
                for (int uu = 0; uu < 8; uu++)
                    e8[uu] = __half2float(w_em[(size_t)(v0 + j2 + uu)*D_ + c]);
                #pragma unroll
                for (int uu = 0; uu < 8; uu++) {
                    A0 = fmaf(u.d.h[0*251 + j2+uu], e8[uu], A0);
                    A1 = fmaf(u.d.h[1*251 + j2+uu], e8[uu], A1);
                    A2 = fmaf(u.d.h[2*251 + j2+uu], e8[uu], A2);
                    A3 = fmaf(u.d.h[3*251 + j2+uu], e8[uu], A3);
                }
            }
            for (; j2 < 251; j2++) {
                float e1 = __half2float(w_em[(size_t)(v0 + j2)*D_ + c]);
                A0 = fmaf(u.d.h[0*251 + j2], e1, A0);
                A1 = fmaf(u.d.h[1*251 + j2], e1, A1);
                A2 = fmaf(u.d.h[2*251 + j2], e1, A2);
                A3 = fmaf(u.d.h[3*251 + j2], e1, A3);
            }
            atomicAdd(&nxt[0*D_ + c], A0);
            atomicAdd(&nxt[1*D_ + c], A1);
            atomicAdd(&nxt[2*D_ + c], A2);
            atomicAdd(&nxt[3*D_ + c], A3);
            __syncthreads();
        }
        gbar(++ep);
        float* tmp = cur; cur = nxt; nxt = tmp;
    }
}

// ---------------- host driver ----------------
extern "C" void kernel_launch(void* const* d_in, const int* in_sizes, int n_in,
                              void* d_out, int out_size) {
    const int*   ids     = (const int*)  d_in[0];
    const float* mask    = (const float*)d_in[1];
    const float* emb     = (const float*)d_in[2];
    const float* enc_wq  = (const float*)d_in[3];
    const float* enc_wk  = (const float*)d_in[4];
    const float* enc_wv  = (const float*)d_in[5];
    const float* enc_wo  = (const float*)d_in[6];
    const float* enc_ln1 = (const float*)d_in[7];
    const float* enc_w1  = (const float*)d_in[8];
    const float* enc_w2  = (const float*)d_in[9];
    const float* enc_ln2 = (const float*)d_in[10];
    const float* enc_lnf = (const float*)d_in[11];
    const float* dec_sq  = (const float*)d_in[12];
    const float* dec_sk  = (const float*)d_in[13];
    const float* dec_sv  = (const float*)d_in[14];
    const float* dec_so  = (const float*)d_in[15];
    const float* dec_ln1 = (const float*)d_in[16];
    const float* dec_cq  = (const float*)d_in[17];
    const float* dec_ck  = (const float*)d_in[18];
    const float* dec_cv  = (const float*)d_in[19];
    const float* dec_co  = (const float*)d_in[20];
    const float* dec_ln2 = (const float*)d_in[21];
    const float* dec_w1  = (const float*)d_in[22];
    const float* dec_w2  = (const float*)d_in[23];
    const float* dec_ln3 = (const float*)d_in[24];
    const float* dec_lnf = (const float*)d_in[25];
    const float* lm_head = (const float*)d_in[26];
    float* out = (float*)d_out;

    k_reset<<<1, 128>>>();
    k_mega<<<NBLK, NTH>>>(ids, mask, emb,
                          enc_wq, enc_wk, enc_wv, enc_wo, enc_ln1,
                          enc_w1, enc_w2, enc_ln2, enc_lnf,
                          dec_sq, dec_sk, dec_sv, dec_so, dec_ln1,
                          dec_cq, dec_ck, dec_cv, dec_co, dec_ln2,
                          dec_w1, dec_w2, dec_ln3, dec_lnf,
                          lm_head, out);
}